// round 16
// baseline (speedup 1.0000x reference)
#include <cuda_runtime.h>
#include <cuda_bf16.h>
#include <cstdint>

// Fused gamma-pdf-weighted MSE mean reduction — single kernel, last-block-done,
// 256-bit L1-bypass loads (ld.global.cv), 6 blocks/SM.
//
// mean( 0.5*(output-target)^2 * ef(target) )
// ef(y) = (BETA - c)*(1 - pdf(y)/FX_MAX) + c,  c = 1/(Y_MAX - Y_MIN)
// pdf/FX_MAX < 4e-19 for fp32 uniform targets except exact zeros ->
// log/exp only in a cold branch (y < 1e-6); hot loop has no MUFU.
//
// R16: the 5.1 TB/s plateau is the clock-scaled LTS ceiling (invariant under
// MLP/width/TMA/hints/prefetch/hybrid across R3-R15). Final knob: occupancy
// fine-tune on the best skeleton (R13). Curve: 39%->28.2, 60%->27.0,
// 94%->28.5 us; probing ~71% (6 blocks/SM).

#define NBLK 888    // 148 SMs * 6
#define NTH  256

__device__ float        g_part[NBLK];
__device__ unsigned int g_count;   // zero-init; self-resetting via atomicInc wrap

__device__ __forceinline__ float elem_val(float o, float y) {
    const float A1        = -0.9355570857535674f;            // EST_A - 1
    const float NEG_LOC   = 1.1328205299926424e-27f;         // -EST_LOC
    const float INV_SCALE = (float)(1.0 / 1.5376362609160314);
    const float C0        = -58.4492351f;                    // -lgamma(a)-ln(scale)-ln(FX_MAX)
    const float C         = (float)(1.0 / 107.2185);
    const float BC        = 5.0f - (float)(1.0 / 107.2185);

    float r = 0.0f;
    if (y < 1e-6f) {                      // cold path: only (near-)zero targets
        float x  = (y + NEG_LOC) * INV_SCALE;
        float lp = fmaf(A1, __logf(x), C0) - x;
        r = __expf(lp);
    }
    float ef   = fmaf(BC, 1.0f - r, C);
    float diff = o - y;
    return 0.5f * diff * diff * ef;
}

// 256-bit global load, L1-bypass (.cv): fetch from L2, no L1 allocation.
__device__ __forceinline__ void ldg256_cv(const float* __restrict__ p, float r[8]) {
    asm volatile("ld.global.cv.v8.f32 {%0,%1,%2,%3,%4,%5,%6,%7}, [%8];"
                 : "=f"(r[0]), "=f"(r[1]), "=f"(r[2]), "=f"(r[3]),
                   "=f"(r[4]), "=f"(r[5]), "=f"(r[6]), "=f"(r[7])
                 : "l"(p));
}

__device__ __forceinline__ float oct_val(const float o[8], const float t[8]) {
    float s = 0.0f;
    #pragma unroll
    for (int j = 0; j < 8; ++j) s += elem_val(o[j], t[j]);
    return s;
}

__global__ __launch_bounds__(NTH, 6) void loss_fused_kernel(
    const float* __restrict__ out, const float* __restrict__ tgt,
    float* __restrict__ result, int n)
{
    const int tid    = threadIdx.x;
    const int lane   = tid & 31;
    const int warp   = tid >> 5;
    const int idx    = blockIdx.x * NTH + tid;
    const int stride = gridDim.x * NTH;
    const int n8     = n >> 3;            // v8 chunks

    float sum = 0.0f;
    int i = idx;

    // Unroll-by-2: 4 x LDG.256 (L1-bypass) issued before compute.
    for (; i + stride < n8; i += 2 * stride) {
        float o0[8], t0[8], o1[8], t1[8];
        ldg256_cv(out + (size_t)i * 8,            o0);
        ldg256_cv(tgt + (size_t)i * 8,            t0);
        ldg256_cv(out + (size_t)(i + stride) * 8, o1);
        ldg256_cv(tgt + (size_t)(i + stride) * 8, t1);
        sum += oct_val(o0, t0);
        sum += oct_val(o1, t1);
    }
    for (; i < n8; i += stride) {          // v8 remainder
        float o0[8], t0[8];
        ldg256_cv(out + (size_t)i * 8, o0);
        ldg256_cv(tgt + (size_t)i * 8, t0);
        sum += oct_val(o0, t0);
    }
    for (int j = (n8 << 3) + idx; j < n; j += stride)   // scalar tail
        sum += elem_val(out[j], tgt[j]);

    // ---- block reduce (full-warp shuffles only) ----
    #pragma unroll
    for (int off = 16; off > 0; off >>= 1)
        sum += __shfl_down_sync(0xFFFFFFFFu, sum, off);

    __shared__ float s_warp[NTH / 32];
    __shared__ bool  s_last;
    if (lane == 0) s_warp[warp] = sum;
    __syncthreads();

    if (warp == 0) {                      // full warp active
        float v = (lane < NTH / 32) ? s_warp[lane] : 0.0f;
        #pragma unroll
        for (int off = 16; off > 0; off >>= 1)
            v += __shfl_down_sync(0xFFFFFFFFu, v, off);
        if (lane == 0) {
            g_part[blockIdx.x] = v;
            __threadfence();                                   // release
            unsigned int prev = atomicInc(&g_count, NBLK - 1u); // wraps -> 0
            s_last = (prev == NBLK - 1u);
        }
    }
    __syncthreads();

    if (s_last) {
        __threadfence();                  // acquire before reading g_part
        double acc = 0.0;                 // fixed-order deterministic reduce
        for (int k = tid; k < NBLK; k += NTH)
            acc += (double)g_part[k];

        #pragma unroll
        for (int off = 16; off > 0; off >>= 1)
            acc += __shfl_down_sync(0xFFFFFFFFu, acc, off);

        __shared__ double s_d[NTH / 32];
        if (lane == 0) s_d[warp] = acc;
        __syncthreads();

        if (warp == 0) {                  // full warp active
            double v = (lane < NTH / 32) ? s_d[lane] : 0.0;
            #pragma unroll
            for (int off = 16; off > 0; off >>= 1)
                v += __shfl_down_sync(0xFFFFFFFFu, v, off);
            if (lane == 0)
                result[0] = (float)(v / (double)n);
        }
    }
}

extern "C" void kernel_launch(void* const* d_in, const int* in_sizes, int n_in,
                              void* d_out, int out_size)
{
    const float* output = (const float*)d_in[0];
    const float* target = (const float*)d_in[1];
    const int n = in_sizes[0];

    loss_fused_kernel<<<NBLK, NTH>>>(output, target, (float*)d_out, n);
}